// round 15
// baseline (speedup 1.0000x reference)
#include <cuda_runtime.h>
#include <cuda_bf16.h>
#include <math.h>
#include <stdint.h>

// Problem constants
#define M_TOK   131072        // B*H*W
#define C_DIM   128
#define N_SEQ   16384
#define NHEADS  4
#define DHEAD   32
#define KS      7

typedef __nv_bfloat16 bf16;

// -------- scratch buffers (static device globals) ---------------------------
__device__ bf16  g_xsb  [(size_t)M_TOK * 128];   // LN2 output (bf16, MLP A)
__device__ bf16  g_qkvb [(size_t)M_TOK * 384];   // qkv (bf16)
__device__ bf16  g_attnb[(size_t)M_TOK * 128];   // attention out (bf16)
__device__ float g_x2   [(size_t)M_TOK * 128];   // residual trunk after proj
__device__ bf16  g_wqkv [384 * 128];
__device__ bf16  g_wproj[128 * 128];
__device__ bf16  g_w1   [512 * 128];
__device__ bf16  g_w2   [128 * 512];

// ---------------------------------------------------------------------------
// PTX helpers
// ---------------------------------------------------------------------------
__device__ __forceinline__ uint32_t smem_u32(const void* p) {
    uint32_t a;
    asm("{ .reg .u64 t; cvta.to.shared.u64 t, %1; cvt.u32.u64 %0, t; }" : "=r"(a) : "l"(p));
    return a;
}
__device__ __forceinline__ void cp_async16(uint32_t dst, const void* src) {
    asm volatile("cp.async.cg.shared.global [%0], [%1], 16;" :: "r"(dst), "l"(src));
}
__device__ __forceinline__ void ldsm4(uint32_t* r, uint32_t addr) {
    asm volatile("ldmatrix.sync.aligned.m8n8.x4.shared.b16 {%0,%1,%2,%3}, [%4];"
                 : "=r"(r[0]), "=r"(r[1]), "=r"(r[2]), "=r"(r[3]) : "r"(addr));
}
__device__ __forceinline__ void mma_bf16(float* c, const uint32_t* a, uint32_t b0, uint32_t b1) {
    asm volatile(
        "mma.sync.aligned.m16n8k16.row.col.f32.bf16.bf16.f32 "
        "{%0,%1,%2,%3}, {%4,%5,%6,%7}, {%8,%9}, {%0,%1,%2,%3};"
        : "+f"(c[0]), "+f"(c[1]), "+f"(c[2]), "+f"(c[3])
        : "r"(a[0]), "r"(a[1]), "r"(a[2]), "r"(a[3]), "r"(b0), "r"(b1));
}

// One 64-wide K-chunk of HMMA on resident swizzled tiles (128B rows, 64 bf16).
// Warp tile 32 rows x 64 cols -> acc[2][8][4].
__device__ __forceinline__ void mma_chunk(uint32_t Ab, uint32_t Bb,
                                          float (&acc)[2][8][4],
                                          int a_row, int a_kof, int b_row, int b_kof)
{
    #pragma unroll
    for (int ks = 0; ks < 4; ks++) {
        uint32_t a[2][4];
        #pragma unroll
        for (int mi = 0; mi < 2; mi++) {
            uint32_t bo = (uint32_t)((a_row + mi * 16) * 128 + (a_kof + ks * 16) * 2);
            ldsm4(a[mi], Ab + (bo ^ ((bo >> 3) & 0x70)));
        }
        #pragma unroll
        for (int nj = 0; nj < 4; nj++) {
            uint32_t b[4];
            uint32_t bo = (uint32_t)((b_row + nj * 16) * 128 + (b_kof + ks * 16) * 2);
            ldsm4(b, Bb + (bo ^ ((bo >> 3) & 0x70)));
            mma_bf16(acc[0][2*nj],   a[0], b[0], b[1]);
            mma_bf16(acc[0][2*nj+1], a[0], b[2], b[3]);
            mma_bf16(acc[1][2*nj],   a[1], b[0], b[1]);
            mma_bf16(acc[1][2*nj+1], a[1], b[2], b[3]);
        }
    }
}

// Streaming loader: one 64-K chunk of A & B tiles from global (row stride KDIM).
template<int KDIM>
__device__ __forceinline__ void load_chunk(uint32_t sbuf,
    const bf16* __restrict__ A, const bf16* __restrict__ Bw,
    int m0, int n0, int c, int tid)
{
    const int r  = tid >> 1;
    const int s0 = (tid & 1) * 4;
    const bf16* Ap = A  + (size_t)(m0 + r) * KDIM + c * 64 + s0 * 8;
    const bf16* Bp = Bw + (size_t)(n0 + r) * KDIM + c * 64 + s0 * 8;
    uint32_t bo0 = (uint32_t)(r * 128 + s0 * 16);
    #pragma unroll
    for (int p = 0; p < 4; p++) {
        uint32_t bo = bo0 + p * 16;
        uint32_t sw = bo ^ ((bo >> 3) & 0x70);
        cp_async16(sbuf + sw,          Ap + p * 8);
        cp_async16(sbuf + 16384u + sw, Bp + p * 8);
    }
    asm volatile("cp.async.commit_group;" ::: "memory");
}

// Resident loader: full 128x128 bf16 tile -> 2-chunk swizzled layout (16KB/chunk).
__device__ __forceinline__ void load_tile(uint32_t dst, const bf16* __restrict__ src,
                                          int rstride, int tid)
{
    const int r  = tid >> 1;
    const int s0 = (tid & 1) * 4;
    const bf16* p = src + (size_t)r * rstride;
    #pragma unroll
    for (int c = 0; c < 2; c++) {
        #pragma unroll
        for (int q = 0; q < 4; q++) {
            uint32_t bo = (uint32_t)(r * 128 + (s0 + q) * 16);
            uint32_t sw = bo ^ ((bo >> 3) & 0x70);
            cp_async16(dst + c * 16384u + sw, p + c * 64 + (s0 + q) * 8);
        }
    }
}

// ---------------------------------------------------------------------------
// Fused weight conversion (all 4 matrices, one launch)
// ---------------------------------------------------------------------------
__global__ void cvt_all(const float* __restrict__ qkvw, const float* __restrict__ projw,
                        const float* __restrict__ fc1w, const float* __restrict__ fc2w,
                        bf16* __restrict__ wqkv, bf16* __restrict__ wproj,
                        bf16* __restrict__ w1, bf16* __restrict__ w2)
{
    int i = blockIdx.x * 256 + threadIdx.x;
    if (i < 49152)        wqkv [i]          = __float2bfloat16_rn(qkvw [i]);
    else if (i < 65536)   wproj[i - 49152]  = __float2bfloat16_rn(projw[i - 49152]);
    else if (i < 131072)  w1   [i - 65536]  = __float2bfloat16_rn(fc1w [i - 65536]);
    else if (i < 196608)  w2   [i - 131072] = __float2bfloat16_rn(fc2w [i - 131072]);
}

// ---------------------------------------------------------------------------
// Fused LN1 + QKV GEMM: one CTA per 128-row M tile, loops over 3 n-tiles
// with the LN1(x) A tile resident in smem. B tiles double-buffered cp.async.
// ---------------------------------------------------------------------------
__global__ __launch_bounds__(256, 2)
void qkv_fused(const float* __restrict__ x,
               const float* __restrict__ n1w, const float* __restrict__ n1b,
               const bf16* __restrict__ Bw, const float* __restrict__ bias,
               bf16* __restrict__ C)
{
    extern __shared__ char dsm[];
    const uint32_t sbase = (smem_u32(dsm) + 127u) & ~127u;
    const uint32_t As = sbase;                    // 32KB (2x16KB chunks)
    const uint32_t Bb0 = sbase + 32768u;          // 32KB
    const uint32_t Bb1 = sbase + 65536u;          // 32KB
    const int tid = threadIdx.x, lane = tid & 31, w = tid >> 5;
    const int wm = w & 3, wn = w >> 2;
    const int m0 = blockIdx.x * 128;

    // stream first two B weight tiles
    load_tile(Bb0, Bw, 128, tid);
    asm volatile("cp.async.commit_group;" ::: "memory");          // G0: B tile n=0
    load_tile(Bb1, Bw + (size_t)128 * 128, 128, tid);
    asm volatile("cp.async.commit_group;" ::: "memory");          // G1: B tile n=1

    // ---- LN1 on the A tile: 2 threads per row (half = 64 cols each) ----
    {
        const int row  = tid >> 1;
        const int half = tid & 1;
        const float4* xp = (const float4*)(x + (size_t)(m0 + row) * 128 + half * 64);
        float s1 = 0.0f, s2 = 0.0f;
        float4 xv[16];
        #pragma unroll
        for (int i = 0; i < 16; i++) {
            float4 v = xp[i];
            xv[i] = v;
            s1 += v.x + v.y + v.z + v.w;
            s2 += v.x*v.x + v.y*v.y + v.z*v.z + v.w*v.w;
        }
        s1 += __shfl_xor_sync(0xffffffffu, s1, 1);
        s2 += __shfl_xor_sync(0xffffffffu, s2, 1);
        float mu   = s1 * (1.0f / 128.0f);
        float rstd = rsqrtf(s2 * (1.0f / 128.0f) - mu * mu + 1e-5f);

        const float4* wp = (const float4*)(n1w + half * 64);
        const float4* bp = (const float4*)(n1b + half * 64);
        const uint32_t Ac = As + (uint32_t)half * 16384u;
        #pragma unroll
        for (int i = 0; i < 16; i++) {
            float4 v = xv[i], w4 = wp[i], b4 = bp[i];
            __nv_bfloat162 p0 = __floats2bfloat162_rn((v.x - mu) * rstd * w4.x + b4.x,
                                                      (v.y - mu) * rstd * w4.y + b4.y);
            __nv_bfloat162 p1 = __floats2bfloat162_rn((v.z - mu) * rstd * w4.z + b4.z,
                                                      (v.w - mu) * rstd * w4.w + b4.w);
            uint32_t bo0 = (uint32_t)(row * 128 + i * 8);
            uint32_t bo1 = bo0 + 4;
            uint32_t a0 = Ac + (bo0 ^ ((bo0 >> 3) & 0x70));
            uint32_t a1 = Ac + (bo1 ^ ((bo1 >> 3) & 0x70));
            asm volatile("st.shared.b32 [%0], %1;" :: "r"(a0), "r"(*(uint32_t*)&p0));
            asm volatile("st.shared.b32 [%0], %1;" :: "r"(a1), "r"(*(uint32_t*)&p1));
        }
    }

    const int a_row = wm * 32 + ((lane >> 3) & 1) * 8 + (lane & 7);
    const int a_kof = (lane >> 4) * 8;
    const int b_row = wn * 64 + (lane >> 4) * 8 + (lane & 7);
    const int b_kof = ((lane >> 3) & 1) * 8;
    const int er = lane >> 2, ec = (lane & 3) * 2;

    #pragma unroll 1
    for (int n = 0; n < 3; n++) {
        if (n < 2) { asm volatile("cp.async.wait_group 1;" ::: "memory"); }
        else       { asm volatile("cp.async.wait_group 0;" ::: "memory"); }
        __syncthreads();   // B buffer ready + (n=0) As stores visible + prior reads done

        const uint32_t Bt = (n & 1) ? Bb1 : Bb0;
        float acc[2][8][4];
        #pragma unroll
        for (int i = 0; i < 2; i++) for (int j = 0; j < 8; j++) for (int q = 0; q < 4; q++)
            acc[i][j][q] = 0.0f;
        #pragma unroll
        for (int c = 0; c < 2; c++)
            mma_chunk(As + c * 16384u, Bt + c * 16384u, acc, a_row, a_kof, b_row, b_kof);

        if (n == 0) {
            __syncthreads();   // all warps done reading Bb0 before overwrite
            load_tile(Bb0, Bw + (size_t)2 * 128 * 128, 128, tid);
            asm volatile("cp.async.commit_group;" ::: "memory");   // G2: B tile n=2
        }

        const int n0 = n * 128;
        #pragma unroll
        for (int mi = 0; mi < 2; mi++) {
            #pragma unroll
            for (int ns = 0; ns < 8; ns++) {
                int row = m0 + wm * 32 + mi * 16 + er;
                int col = n0 + wn * 64 + ns * 8 + ec;
                float2 bb = *(const float2*)&bias[col];
                *(__nv_bfloat162*)&C[(size_t)row * 384 + col] =
                    __floats2bfloat162_rn(acc[mi][ns][0] + bb.x, acc[mi][ns][1] + bb.y);
                *(__nv_bfloat162*)&C[(size_t)(row + 8) * 384 + col] =
                    __floats2bfloat162_rn(acc[mi][ns][2] + bb.x, acc[mi][ns][3] + bb.y);
            }
        }
    }
}

// ---------------------------------------------------------------------------
// Sliding-window attention, v3: d-split 2 threads per (token,head).
// ---------------------------------------------------------------------------
#define SLOTS 38
#define SLOTP 39
__device__ __forceinline__ float bf_lo(uint32_t w) { return __uint_as_float(w << 16); }
__device__ __forceinline__ float bf_hi(uint32_t w) { return __uint_as_float(w & 0xffff0000u); }

__global__ __launch_bounds__(256, 4)
void attn_kernel(const bf16* __restrict__ qkv, const float* __restrict__ rpb,
                 bf16* __restrict__ out)
{
    __shared__ float ks[4 * 32 * SLOTP];
    __shared__ float vs[4 * 32 * SLOTP];

    const int tid  = threadIdx.x;
    const int wid  = tid >> 5;
    const int lane = tid & 31;
    const int t0   = blockIdx.x * 32;
    const int n0   = t0 & (N_SEQ - 1);
    const int bb   = t0 - n0;

    #pragma unroll 1
    for (int task = wid; task < 2 * SLOTS; task += 8) {
        int slot = task >> 1, kv = task & 1;
        int nn = n0 - 3 + slot;
        nn = min(max(nn, 0), N_SEQ - 1);
        const uint2* src = (const uint2*)(qkv + (size_t)(bb + nn) * 384 + 128 + kv * 128);
        uint2 w2 = src[lane];
        int h  = lane >> 3;
        int d0 = (4 * lane) & 31;
        float* dst = (kv ? vs : ks) + (h * 32 + d0) * SLOTP + slot;
        dst[0 * SLOTP] = bf_lo(w2.x);
        dst[1 * SLOTP] = bf_hi(w2.x);
        dst[2 * SLOTP] = bf_lo(w2.y);
        dst[3 * SLOTP] = bf_hi(w2.y);
    }
    __syncthreads();

    const int h      = wid & 3;
    const int tgroup = wid >> 2;
    const int tsub   = lane >> 1;
    const int half   = lane & 1;
    const int n      = n0 + tgroup * 16 + tsub;
    const size_t t   = (size_t)(t0 + tgroup * 16 + tsub);

    float q[16];
    {
        const uint4* qp = (const uint4*)&qkv[t * 384 + h * 32 + half * 16];
        #pragma unroll
        for (int u = 0; u < 2; u++) {
            uint4 raw = qp[u];
            const uint32_t* pr = (const uint32_t*)&raw;
            #pragma unroll
            for (int p = 0; p < 4; p++) {
                q[u * 8 + p * 2]     = bf_lo(pr[p]) * 0.17677669529663687f;
                q[u * 8 + p * 2 + 1] = bf_hi(pr[p]) * 0.17677669529663687f;
            }
        }
    }

    int s = n - 3;
    if (s < 0) s = 0;
    if (s > N_SEQ - 7) s = N_SEQ - 7;
    const int slot0 = s - n0 + 3;

    float logits[KS];
    const float* kb = &ks[(h * 32 + half * 16) * SLOTP + slot0];
    #pragma unroll
    for (int j = 0; j < KS; j++) {
        float acc = 0.0f;
        const float* kp = kb + j;
        #pragma unroll
        for (int dd = 0; dd < 16; dd++) acc += q[dd] * kp[dd * SLOTP];
        acc += __shfl_xor_sync(0xffffffffu, acc, 1);
        logits[j] = acc + rpb[h * (2 * KS - 1) + (s + j - n + 6)];
    }

    float mx = logits[0];
    #pragma unroll
    for (int j = 1; j < KS; j++) mx = fmaxf(mx, logits[j]);
    float pj[KS], den = 0.0f;
    #pragma unroll
    for (int j = 0; j < KS; j++) { pj[j] = __expf(logits[j] - mx); den += pj[j]; }
    const float inv = 1.0f / den;

    float o[16];
    #pragma unroll
    for (int dd = 0; dd < 16; dd++) o[dd] = 0.0f;
    const float* vb = &vs[(h * 32 + half * 16) * SLOTP + slot0];
    #pragma unroll
    for (int j = 0; j < KS; j++) {
        const float p = pj[j] * inv;
        const float* vp = vb + j;
        #pragma unroll
        for (int dd = 0; dd < 16; dd++) o[dd] += p * vp[dd * SLOTP];
    }

    __nv_bfloat162 ob[8];
    #pragma unroll
    for (int i = 0; i < 8; i++) ob[i] = __floats2bfloat162_rn(o[2 * i], o[2 * i + 1]);
    uint4* op = (uint4*)&out[t * 128 + h * 32 + half * 16];
    op[0] = ((uint4*)ob)[0];
    op[1] = ((uint4*)ob)[1];
}

// ---------------------------------------------------------------------------
// Proj GEMM + residual + fused LN2: writes x2 (fp32) and xsb=LN2(x2) (bf16).
// ---------------------------------------------------------------------------
__global__ __launch_bounds__(256, 2)
void proj_ln(const bf16* __restrict__ A, const bf16* __restrict__ Bw,
             const float* __restrict__ bias, const float* __restrict__ res,
             const float* __restrict__ n2w, const float* __restrict__ n2b,
             float* __restrict__ x2, bf16* __restrict__ xsb)
{
    extern __shared__ char dsm[];
    __shared__ float rs[128], rq[128], smu[128], sst[128];
    const uint32_t sbase = (smem_u32(dsm) + 127u) & ~127u;
    const int tid = threadIdx.x, lane = tid & 31, w = tid >> 5;
    const int wm = w & 3, wn = w >> 2;
    const int m0 = blockIdx.x * 128;

    if (tid < 128) { rs[tid] = 0.0f; rq[tid] = 0.0f; }

    float acc[2][8][4];
    #pragma unroll
    for (int i = 0; i < 2; i++) for (int j = 0; j < 8; j++) for (int q = 0; q < 4; q++)
        acc[i][j][q] = 0.0f;

    const int a_row = wm * 32 + ((lane >> 3) & 1) * 8 + (lane & 7);
    const int a_kof = (lane >> 4) * 8;
    const int b_row = wn * 64 + (lane >> 4) * 8 + (lane & 7);
    const int b_kof = ((lane >> 3) & 1) * 8;

    load_chunk<128>(sbase, A, Bw, m0, 0, 0, tid);
    load_chunk<128>(sbase + 32768u, A, Bw, m0, 0, 1, tid);
    asm volatile("cp.async.wait_group 1;" ::: "memory");
    __syncthreads();
    mma_chunk(sbase, sbase + 16384u, acc, a_row, a_kof, b_row, b_kof);
    asm volatile("cp.async.wait_group 0;" ::: "memory");
    __syncthreads();
    mma_chunk(sbase + 32768u, sbase + 49152u, acc, a_row, a_kof, b_row, b_kof);

    const int er = lane >> 2, ec = (lane & 3) * 2;
    float ps0[2] = {0, 0}, ps1[2] = {0, 0}, pq0[2] = {0, 0}, pq1[2] = {0, 0};
    #pragma unroll
    for (int mi = 0; mi < 2; mi++) {
        #pragma unroll
        for (int ns = 0; ns < 8; ns++) {
            int lr  = wm * 32 + mi * 16 + er;
            int col = wn * 64 + ns * 8 + ec;
            int row = m0 + lr;
            float2 bb = *(const float2*)&bias[col];
            float2 r0 = *(const float2*)&res[(size_t)row * 128 + col];
            float2 r1 = *(const float2*)&res[(size_t)(row + 8) * 128 + col];
            float v0 = acc[mi][ns][0] + bb.x + r0.x;
            float v1 = acc[mi][ns][1] + bb.y + r0.y;
            float v2 = acc[mi][ns][2] + bb.x + r1.x;
            float v3 = acc[mi][ns][3] + bb.y + r1.y;
            acc[mi][ns][0] = v0; acc[mi][ns][1] = v1;
            acc[mi][ns][2] = v2; acc[mi][ns][3] = v3;
            *(float2*)&x2[(size_t)row * 128 + col]       = make_float2(v0, v1);
            *(float2*)&x2[(size_t)(row + 8) * 128 + col] = make_float2(v2, v3);
            ps0[mi] += v0 + v1;          pq0[mi] += v0*v0 + v1*v1;
            ps1[mi] += v2 + v3;          pq1[mi] += v2*v2 + v3*v3;
        }
    }
    #pragma unroll
    for (int mi = 0; mi < 2; mi++) {
        int lr = wm * 32 + mi * 16 + er;
        atomicAdd(&rs[lr], ps0[mi]);      atomicAdd(&rq[lr], pq0[mi]);
        atomicAdd(&rs[lr + 8], ps1[mi]);  atomicAdd(&rq[lr + 8], pq1[mi]);
    }
    __syncthreads();
    if (tid < 128) {
        float mu  = rs[tid] * (1.0f / 128.0f);
        float var = rq[tid] * (1.0f / 128.0f) - mu * mu;
        smu[tid] = mu;
        sst[tid] = rsqrtf(var + 1e-5f);
    }
    __syncthreads();

    #pragma unroll
    for (int mi = 0; mi < 2; mi++) {
        #pragma unroll
        for (int ns = 0; ns < 8; ns++) {
            int lr  = wm * 32 + mi * 16 + er;
            int col = wn * 64 + ns * 8 + ec;
            int row = m0 + lr;
            float2 wv = *(const float2*)&n2w[col];
            float2 bv = *(const float2*)&n2b[col];
            float mu0 = smu[lr],     st0 = sst[lr];
            float mu1 = smu[lr + 8], st1 = sst[lr + 8];
            *(__nv_bfloat162*)&xsb[(size_t)row * 128 + col] =
                __floats2bfloat162_rn((acc[mi][ns][0] - mu0) * st0 * wv.x + bv.x,
                                      (acc[mi][ns][1] - mu0) * st0 * wv.y + bv.y);
            *(__nv_bfloat162*)&xsb[(size_t)(row + 8) * 128 + col] =
                __floats2bfloat162_rn((acc[mi][ns][2] - mu1) * st1 * wv.x + bv.x,
                                      (acc[mi][ns][3] - mu1) * st1 * wv.y + bv.y);
        }
    }
}

// ---------------------------------------------------------------------------
// Fused MLP (v1): out = x2 + fc2( gelu( fc1(xsb) ) ), h never hits DRAM.
// ---------------------------------------------------------------------------
__global__ __launch_bounds__(256, 1)
void mlp_kernel(const bf16* __restrict__ Axs,
                const bf16* __restrict__ w1, const float* __restrict__ b1,
                const bf16* __restrict__ w2, const float* __restrict__ b2,
                const float* __restrict__ x2, float* __restrict__ out)
{
    extern __shared__ char dsm[];
    const uint32_t sbase = (smem_u32(dsm) + 127u) & ~127u;
    const uint32_t As = sbase, Hs = sbase + 32768u, B0 = sbase + 65536u, B1 = sbase + 98304u;
    const int tid = threadIdx.x, lane = tid & 31, w = tid >> 5;
    const int wm = w & 3, wn = w >> 2;
    const int m0 = blockIdx.x * 128;

    const int a_row = wm * 32 + ((lane >> 3) & 1) * 8 + (lane & 7);
    const int a_kof = (lane >> 4) * 8;
    const int b_row = wn * 64 + (lane >> 4) * 8 + (lane & 7);
    const int b_kof = ((lane >> 3) & 1) * 8;
    const int er = lane >> 2, ec = (lane & 3) * 2;

    float oacc[2][8][4];
    #pragma unroll
    for (int i = 0; i < 2; i++) for (int j = 0; j < 8; j++) for (int q = 0; q < 4; q++)
        oacc[i][j][q] = 0.0f;

    load_tile(As, Axs + (size_t)m0 * 128, 128, tid);
    load_tile(B0, w1, 128, tid);
    asm volatile("cp.async.commit_group;" ::: "memory");
    load_tile(B1, w2, 512, tid);
    asm volatile("cp.async.commit_group;" ::: "memory");

    #pragma unroll 1
    for (int j = 0; j < 4; j++) {
        asm volatile("cp.async.wait_group 1;" ::: "memory");
        __syncthreads();

        float hacc[2][8][4];
        #pragma unroll
        for (int i = 0; i < 2; i++) for (int jj = 0; jj < 8; jj++) for (int q = 0; q < 4; q++)
            hacc[i][jj][q] = 0.0f;
        #pragma unroll
        for (int c = 0; c < 2; c++)
            mma_chunk(As + c * 16384u, B0 + c * 16384u, hacc, a_row, a_kof, b_row, b_kof);

        #pragma unroll
        for (int mi = 0; mi < 2; mi++) {
            #pragma unroll
            for (int ns = 0; ns < 8; ns++) {
                int lr  = wm * 32 + mi * 16 + er;
                int col = wn * 64 + ns * 8 + ec;
                float2 bb = *(const float2*)&b1[j * 128 + col];
                float v0 = hacc[mi][ns][0] + bb.x;
                float v1 = hacc[mi][ns][1] + bb.y;
                float v2 = hacc[mi][ns][2] + bb.x;
                float v3 = hacc[mi][ns][3] + bb.y;
                const float cst = 0.70710678118654752f;
                v0 = 0.5f * v0 * (1.0f + erff(v0 * cst));
                v1 = 0.5f * v1 * (1.0f + erff(v1 * cst));
                v2 = 0.5f * v2 * (1.0f + erff(v2 * cst));
                v3 = 0.5f * v3 * (1.0f + erff(v3 * cst));
                uint32_t ch = (uint32_t)(col >> 6) * 16384u;
                int cc = col & 63;
                uint32_t bo0 = (uint32_t)(lr * 128 + cc * 2);
                uint32_t bo1 = (uint32_t)((lr + 8) * 128 + cc * 2);
                uint32_t ad0 = Hs + ch + (bo0 ^ ((bo0 >> 3) & 0x70));
                uint32_t ad1 = Hs + ch + (bo1 ^ ((bo1 >> 3) & 0x70));
                __nv_bfloat162 p0 = __floats2bfloat162_rn(v0, v1);
                __nv_bfloat162 p1 = __floats2bfloat162_rn(v2, v3);
                asm volatile("st.shared.b32 [%0], %1;" :: "r"(ad0), "r"(*(uint32_t*)&p0));
                asm volatile("st.shared.b32 [%0], %1;" :: "r"(ad1), "r"(*(uint32_t*)&p1));
            }
        }
        __syncthreads();
        if (j < 3) {
            load_tile(B0, w1 + (size_t)(j + 1) * 128 * 128, 128, tid);
            asm volatile("cp.async.commit_group;" ::: "memory");
        }
        if (j < 3) { asm volatile("cp.async.wait_group 1;" ::: "memory"); }
        else       { asm volatile("cp.async.wait_group 0;" ::: "memory"); }
        __syncthreads();

        #pragma unroll
        for (int c = 0; c < 2; c++)
            mma_chunk(Hs + c * 16384u, B1 + c * 16384u, oacc, a_row, a_kof, b_row, b_kof);
        __syncthreads();
        if (j < 3) {
            load_tile(B1, w2 + (size_t)(j + 1) * 128, 512, tid);
            asm volatile("cp.async.commit_group;" ::: "memory");
        }
    }

    #pragma unroll
    for (int mi = 0; mi < 2; mi++) {
        #pragma unroll
        for (int ns = 0; ns < 8; ns++) {
            int lr  = wm * 32 + mi * 16 + er;
            int col = wn * 64 + ns * 8 + ec;
            int row = m0 + lr;
            float2 bb = *(const float2*)&b2[col];
            float2 r0 = *(const float2*)&x2[(size_t)row * 128 + col];
            float2 r1 = *(const float2*)&x2[(size_t)(row + 8) * 128 + col];
            *(float2*)&out[(size_t)row * 128 + col] =
                make_float2(oacc[mi][ns][0] + bb.x + r0.x, oacc[mi][ns][1] + bb.y + r0.y);
            *(float2*)&out[(size_t)(row + 8) * 128 + col] =
                make_float2(oacc[mi][ns][2] + bb.x + r1.x, oacc[mi][ns][3] + bb.y + r1.y);
        }
    }
}

// ---------------------------------------------------------------------------
extern "C" void kernel_launch(void* const* d_in, const int* in_sizes, int n_in,
                              void* d_out, int out_size)
{
    const float* x      = (const float*)d_in[0];
    const float* n1w    = (const float*)d_in[1];
    const float* n1b    = (const float*)d_in[2];
    const float* qkvw   = (const float*)d_in[3];
    const float* qkvb   = (const float*)d_in[4];
    const float* rpb    = (const float*)d_in[5];
    const float* projw  = (const float*)d_in[6];
    const float* projb  = (const float*)d_in[7];
    const float* n2w    = (const float*)d_in[8];
    const float* n2b    = (const float*)d_in[9];
    const float* fc1w   = (const float*)d_in[10];
    const float* fc1b   = (const float*)d_in[11];
    const float* fc2w   = (const float*)d_in[12];
    const float* fc2b   = (const float*)d_in[13];
    float* out = (float*)d_out;

    bf16 *xsb, *qkvb_s, *attnb, *wqkv, *wproj, *w1, *w2;
    float *x2;
    cudaGetSymbolAddress((void**)&xsb,    g_xsb);
    cudaGetSymbolAddress((void**)&qkvb_s, g_qkvb);
    cudaGetSymbolAddress((void**)&attnb,  g_attnb);
    cudaGetSymbolAddress((void**)&x2,     g_x2);
    cudaGetSymbolAddress((void**)&wqkv,   g_wqkv);
    cudaGetSymbolAddress((void**)&wproj,  g_wproj);
    cudaGetSymbolAddress((void**)&w1,     g_w1);
    cudaGetSymbolAddress((void**)&w2,     g_w2);

    const int SMEM_Q = 98304 + 128;
    const int SMEM_G = 65536 + 128;
    const int SMEM_M = 131072 + 128;
    cudaFuncSetAttribute(qkv_fused,  cudaFuncAttributeMaxDynamicSharedMemorySize, SMEM_Q);
    cudaFuncSetAttribute(proj_ln,    cudaFuncAttributeMaxDynamicSharedMemorySize, SMEM_G);
    cudaFuncSetAttribute(mlp_kernel, cudaFuncAttributeMaxDynamicSharedMemorySize, SMEM_M);

    // 0. weights -> bf16
    cvt_all<<<768, 256>>>(qkvw, projw, fc1w, fc2w, wqkv, wproj, w1, w2);
    // 1. fused LN1 + QKV projection -> bf16
    qkv_fused<<<M_TOK / 128, 256, SMEM_Q>>>(x, n1w, n1b, wqkv, qkvb, qkvb_s);
    // 2. attention -> bf16 (d-split, 256 threads / 32 tokens)
    attn_kernel<<<M_TOK / 32, 256>>>(qkvb_s, rpb, attnb);
    // 3. proj + residual + LN2 -> x2 (fp32) + xsb (bf16)
    proj_ln<<<M_TOK / 128, 256, SMEM_G>>>(attnb, wproj, projb, x, n2w, n2b, x2, xsb);
    // 4. fused MLP -> out
    mlp_kernel<<<M_TOK / 128, 256, SMEM_M>>>(xsb, w1, fc1b, w2, fc2b, x2, out);
}

// round 16
// speedup vs baseline: 1.0305x; 1.0305x over previous
#include <cuda_runtime.h>
#include <cuda_bf16.h>
#include <math.h>
#include <stdint.h>

// Problem constants
#define M_TOK   131072        // B*H*W
#define C_DIM   128
#define N_SEQ   16384
#define NHEADS  4
#define DHEAD   32
#define KS      7

typedef __nv_bfloat16 bf16;

// -------- scratch buffers (static device globals) ---------------------------
__device__ bf16  g_xsb  [(size_t)M_TOK * 128];   // LN output (bf16 GEMM A)
__device__ bf16  g_qkvb [(size_t)M_TOK * 384];   // qkv (bf16)
__device__ bf16  g_attnb[(size_t)M_TOK * 128];   // attention out (bf16)
__device__ float g_x2   [(size_t)M_TOK * 128];   // residual trunk after proj
__device__ bf16  g_wqkv [384 * 128];
__device__ bf16  g_wproj[128 * 128];
__device__ bf16  g_w1   [512 * 128];
__device__ bf16  g_w2   [128 * 512];

// ---------------------------------------------------------------------------
// PTX helpers
// ---------------------------------------------------------------------------
__device__ __forceinline__ uint32_t smem_u32(const void* p) {
    uint32_t a;
    asm("{ .reg .u64 t; cvta.to.shared.u64 t, %1; cvt.u32.u64 %0, t; }" : "=r"(a) : "l"(p));
    return a;
}
__device__ __forceinline__ void cp_async16(uint32_t dst, const void* src) {
    asm volatile("cp.async.cg.shared.global [%0], [%1], 16;" :: "r"(dst), "l"(src));
}
__device__ __forceinline__ void ldsm4(uint32_t* r, uint32_t addr) {
    asm volatile("ldmatrix.sync.aligned.m8n8.x4.shared.b16 {%0,%1,%2,%3}, [%4];"
                 : "=r"(r[0]), "=r"(r[1]), "=r"(r[2]), "=r"(r[3]) : "r"(addr));
}
__device__ __forceinline__ void mma_bf16(float* c, const uint32_t* a, uint32_t b0, uint32_t b1) {
    asm volatile(
        "mma.sync.aligned.m16n8k16.row.col.f32.bf16.bf16.f32 "
        "{%0,%1,%2,%3}, {%4,%5,%6,%7}, {%8,%9}, {%0,%1,%2,%3};"
        : "+f"(c[0]), "+f"(c[1]), "+f"(c[2]), "+f"(c[3])
        : "r"(a[0]), "r"(a[1]), "r"(a[2]), "r"(a[3]), "r"(b0), "r"(b1));
}

// One 64-wide K-chunk of HMMA on resident swizzled tiles (128B rows, 64 bf16).
__device__ __forceinline__ void mma_chunk(uint32_t Ab, uint32_t Bb,
                                          float (&acc)[2][8][4],
                                          int a_row, int a_kof, int b_row, int b_kof)
{
    #pragma unroll
    for (int ks = 0; ks < 4; ks++) {
        uint32_t a[2][4];
        #pragma unroll
        for (int mi = 0; mi < 2; mi++) {
            uint32_t bo = (uint32_t)((a_row + mi * 16) * 128 + (a_kof + ks * 16) * 2);
            ldsm4(a[mi], Ab + (bo ^ ((bo >> 3) & 0x70)));
        }
        #pragma unroll
        for (int nj = 0; nj < 4; nj++) {
            uint32_t b[4];
            uint32_t bo = (uint32_t)((b_row + nj * 16) * 128 + (b_kof + ks * 16) * 2);
            ldsm4(b, Bb + (bo ^ ((bo >> 3) & 0x70)));
            mma_bf16(acc[0][2*nj],   a[0], b[0], b[1]);
            mma_bf16(acc[0][2*nj+1], a[0], b[2], b[3]);
            mma_bf16(acc[1][2*nj],   a[1], b[0], b[1]);
            mma_bf16(acc[1][2*nj+1], a[1], b[2], b[3]);
        }
    }
}

// Streaming loader: one 64-K chunk of A & B tiles from global (row stride KDIM).
template<int KDIM>
__device__ __forceinline__ void load_chunk(uint32_t sbuf,
    const bf16* __restrict__ A, const bf16* __restrict__ Bw,
    int m0, int n0, int c, int tid)
{
    const int r  = tid >> 1;
    const int s0 = (tid & 1) * 4;
    const bf16* Ap = A  + (size_t)(m0 + r) * KDIM + c * 64 + s0 * 8;
    const bf16* Bp = Bw + (size_t)(n0 + r) * KDIM + c * 64 + s0 * 8;
    uint32_t bo0 = (uint32_t)(r * 128 + s0 * 16);
    #pragma unroll
    for (int p = 0; p < 4; p++) {
        uint32_t bo = bo0 + p * 16;
        uint32_t sw = bo ^ ((bo >> 3) & 0x70);
        cp_async16(sbuf + sw,          Ap + p * 8);
        cp_async16(sbuf + 16384u + sw, Bp + p * 8);
    }
    asm volatile("cp.async.commit_group;" ::: "memory");
}

// Resident loader: full 128x128 bf16 tile -> 2-chunk swizzled layout (16KB/chunk).
__device__ __forceinline__ void load_tile(uint32_t dst, const bf16* __restrict__ src,
                                          int rstride, int tid)
{
    const int r  = tid >> 1;
    const int s0 = (tid & 1) * 4;
    const bf16* p = src + (size_t)r * rstride;
    #pragma unroll
    for (int c = 0; c < 2; c++) {
        #pragma unroll
        for (int q = 0; q < 4; q++) {
            uint32_t bo = (uint32_t)(r * 128 + (s0 + q) * 16);
            uint32_t sw = bo ^ ((bo >> 3) & 0x70);
            cp_async16(dst + c * 16384u + sw, p + c * 64 + (s0 + q) * 8);
        }
    }
}

// ---------------------------------------------------------------------------
// LayerNorm (LN1): one warp per row, bf16 output.
// ---------------------------------------------------------------------------
__global__ __launch_bounds__(256)
void ln_kernel(const float* __restrict__ x, const float* __restrict__ w,
               const float* __restrict__ b, bf16* __restrict__ out)
{
    int row  = blockIdx.x * 8 + (threadIdx.x >> 5);
    int lane = threadIdx.x & 31;
    const float4 v = ((const float4*)(x + (size_t)row * 128))[lane];

    float s = v.x + v.y + v.z + v.w;
    #pragma unroll
    for (int o = 16; o; o >>= 1) s += __shfl_xor_sync(0xffffffffu, s, o);
    float mu = s * (1.0f / 128.0f);

    float dx = v.x - mu, dy = v.y - mu, dz = v.z - mu, dw = v.w - mu;
    float sq = dx*dx + dy*dy + dz*dz + dw*dw;
    #pragma unroll
    for (int o = 16; o; o >>= 1) sq += __shfl_xor_sync(0xffffffffu, sq, o);
    float rstd = rsqrtf(sq * (1.0f / 128.0f) + 1e-5f);

    const float4 wv = ((const float4*)w)[lane];
    const float4 bv = ((const float4*)b)[lane];
    __nv_bfloat162* op = (__nv_bfloat162*)(out + (size_t)row * 128 + lane * 4);
    op[0] = __floats2bfloat162_rn(dx * rstd * wv.x + bv.x, dy * rstd * wv.y + bv.y);
    op[1] = __floats2bfloat162_rn(dz * rstd * wv.z + bv.z, dw * rstd * wv.w + bv.w);
}

// ---------------------------------------------------------------------------
// Fused weight conversion (all 4 matrices, one launch)
// ---------------------------------------------------------------------------
__global__ void cvt_all(const float* __restrict__ qkvw, const float* __restrict__ projw,
                        const float* __restrict__ fc1w, const float* __restrict__ fc2w,
                        bf16* __restrict__ wqkv, bf16* __restrict__ wproj,
                        bf16* __restrict__ w1, bf16* __restrict__ w2)
{
    int i = blockIdx.x * 256 + threadIdx.x;
    if (i < 49152)        wqkv [i]          = __float2bfloat16_rn(qkvw [i]);
    else if (i < 65536)   wproj[i - 49152]  = __float2bfloat16_rn(projw[i - 49152]);
    else if (i < 131072)  w1   [i - 65536]  = __float2bfloat16_rn(fc1w [i - 65536]);
    else if (i < 196608)  w2   [i - 131072] = __float2bfloat16_rn(fc2w [i - 131072]);
}

// ---------------------------------------------------------------------------
// QKV GEMM: C[M,384] = xsb @ wqkv^T + bias, bf16 out. K=128.
// ---------------------------------------------------------------------------
__global__ __launch_bounds__(256, 2)
void gemm_qkv(const bf16* __restrict__ A, const bf16* __restrict__ Bw,
              const float* __restrict__ bias, bf16* __restrict__ C)
{
    extern __shared__ char dsm[];
    const uint32_t sbase = (smem_u32(dsm) + 127u) & ~127u;
    const int tid = threadIdx.x, lane = tid & 31, w = tid >> 5;
    const int wm = w & 3, wn = w >> 2;
    const int m0 = blockIdx.y * 128, n0 = blockIdx.x * 128;

    float acc[2][8][4];
    #pragma unroll
    for (int i = 0; i < 2; i++) for (int j = 0; j < 8; j++) for (int q = 0; q < 4; q++)
        acc[i][j][q] = 0.0f;

    const int a_row = wm * 32 + ((lane >> 3) & 1) * 8 + (lane & 7);
    const int a_kof = (lane >> 4) * 8;
    const int b_row = wn * 64 + (lane >> 4) * 8 + (lane & 7);
    const int b_kof = ((lane >> 3) & 1) * 8;

    load_chunk<128>(sbase, A, Bw, m0, n0, 0, tid);
    load_chunk<128>(sbase + 32768u, A, Bw, m0, n0, 1, tid);
    asm volatile("cp.async.wait_group 1;" ::: "memory");
    __syncthreads();
    mma_chunk(sbase, sbase + 16384u, acc, a_row, a_kof, b_row, b_kof);
    asm volatile("cp.async.wait_group 0;" ::: "memory");
    __syncthreads();
    mma_chunk(sbase + 32768u, sbase + 49152u, acc, a_row, a_kof, b_row, b_kof);

    const int er = lane >> 2, ec = (lane & 3) * 2;
    #pragma unroll
    for (int mi = 0; mi < 2; mi++) {
        #pragma unroll
        for (int ns = 0; ns < 8; ns++) {
            int row = m0 + wm * 32 + mi * 16 + er;
            int col = n0 + wn * 64 + ns * 8 + ec;
            float2 bb = *(const float2*)&bias[col];
            *(__nv_bfloat162*)&C[(size_t)row * 384 + col] =
                __floats2bfloat162_rn(acc[mi][ns][0] + bb.x, acc[mi][ns][1] + bb.y);
            *(__nv_bfloat162*)&C[(size_t)(row + 8) * 384 + col] =
                __floats2bfloat162_rn(acc[mi][ns][2] + bb.x, acc[mi][ns][3] + bb.y);
        }
    }
}

// ---------------------------------------------------------------------------
// Sliding-window attention, v4: d-split + PACKED bf16x2 smem.
// k/v halo stored as bf16x2 words [h][dpair][slot] (SLOTP=39 words, odd ->
// bank spread). Compute loop: 1 LDS per d-pair (8 per j per k/v) + unpack on
// the ALU pipe. Staging stores the loaded uint2 verbatim (no cvt).
// ---------------------------------------------------------------------------
#define SLOTS 38
#define SLOTP 39
__device__ __forceinline__ float bf_lo(uint32_t w) { return __uint_as_float(w << 16); }
__device__ __forceinline__ float bf_hi(uint32_t w) { return __uint_as_float(w & 0xffff0000u); }

__global__ __launch_bounds__(256, 4)
void attn_kernel(const bf16* __restrict__ qkv, const float* __restrict__ rpb,
                 bf16* __restrict__ out)
{
    __shared__ uint32_t ks[4 * 16 * SLOTP];   // [h][dpair][slot] bf16x2
    __shared__ uint32_t vs[4 * 16 * SLOTP];

    const int tid  = threadIdx.x;
    const int wid  = tid >> 5;
    const int lane = tid & 31;
    const int t0   = blockIdx.x * 32;
    const int n0   = t0 & (N_SEQ - 1);
    const int bb   = t0 - n0;

    // ---- staging: 76 row-tasks (38 slots x {k,v}), one warp-row each ----
    #pragma unroll 1
    for (int task = wid; task < 2 * SLOTS; task += 8) {
        int slot = task >> 1, kv = task & 1;
        int nn = n0 - 3 + slot;
        nn = min(max(nn, 0), N_SEQ - 1);
        const uint2* src = (const uint2*)(qkv + (size_t)(bb + nn) * 384 + 128 + kv * 128);
        uint2 w2 = src[lane];                       // 4 bf16 = 2 packed words
        int h   = lane >> 3;
        int dp0 = (lane & 7) * 2;                   // pair index 0..14
        uint32_t* dst = (kv ? vs : ks) + (h * 16 + dp0) * SLOTP + slot;
        dst[0]     = w2.x;
        dst[SLOTP] = w2.y;
    }
    __syncthreads();

    // ---- compute ----
    const int h      = wid & 3;
    const int tgroup = wid >> 2;
    const int tsub   = lane >> 1;
    const int half   = lane & 1;
    const int n      = n0 + tgroup * 16 + tsub;
    const size_t t   = (size_t)(t0 + tgroup * 16 + tsub);

    // q half (16 d's), scaled; q[i] = d (half*16 + i)
    float q[16];
    {
        const uint4* qp = (const uint4*)&qkv[t * 384 + h * 32 + half * 16];
        #pragma unroll
        for (int u = 0; u < 2; u++) {
            uint4 raw = qp[u];
            const uint32_t* pr = (const uint32_t*)&raw;
            #pragma unroll
            for (int p = 0; p < 4; p++) {
                q[u * 8 + p * 2]     = bf_lo(pr[p]) * 0.17677669529663687f;
                q[u * 8 + p * 2 + 1] = bf_hi(pr[p]) * 0.17677669529663687f;
            }
        }
    }

    int s = n - 3;
    if (s < 0) s = 0;
    if (s > N_SEQ - 7) s = N_SEQ - 7;
    const int slot0 = s - n0 + 3;

    // logits: partial over this thread's 16 d's (8 packed words per j)
    float logits[KS];
    const uint32_t* kb = &ks[(h * 16 + half * 8) * SLOTP + slot0];
    #pragma unroll
    for (int j = 0; j < KS; j++) {
        float acc = 0.0f;
        const uint32_t* kp = kb + j;
        #pragma unroll
        for (int dp = 0; dp < 8; dp++) {
            uint32_t wv = kp[dp * SLOTP];
            acc += q[2 * dp] * bf_lo(wv) + q[2 * dp + 1] * bf_hi(wv);
        }
        acc += __shfl_xor_sync(0xffffffffu, acc, 1);
        logits[j] = acc + rpb[h * (2 * KS - 1) + (s + j - n + 6)];
    }

    float mx = logits[0];
    #pragma unroll
    for (int j = 1; j < KS; j++) mx = fmaxf(mx, logits[j]);
    float pj[KS], den = 0.0f;
    #pragma unroll
    for (int j = 0; j < KS; j++) { pj[j] = __expf(logits[j] - mx); den += pj[j]; }
    const float inv = 1.0f / den;

    // o: this thread's 16 d's
    float o[16];
    #pragma unroll
    for (int dd = 0; dd < 16; dd++) o[dd] = 0.0f;
    const uint32_t* vb = &vs[(h * 16 + half * 8) * SLOTP + slot0];
    #pragma unroll
    for (int j = 0; j < KS; j++) {
        const float p = pj[j] * inv;
        const uint32_t* vp = vb + j;
        #pragma unroll
        for (int dp = 0; dp < 8; dp++) {
            uint32_t wv = vp[dp * SLOTP];
            o[2 * dp]     += p * bf_lo(wv);
            o[2 * dp + 1] += p * bf_hi(wv);
        }
    }

    __nv_bfloat162 ob[8];
    #pragma unroll
    for (int i = 0; i < 8; i++) ob[i] = __floats2bfloat162_rn(o[2 * i], o[2 * i + 1]);
    uint4* op = (uint4*)&out[t * 128 + h * 32 + half * 16];
    op[0] = ((uint4*)ob)[0];
    op[1] = ((uint4*)ob)[1];
}

// ---------------------------------------------------------------------------
// Proj GEMM + residual + fused LN2: writes x2 (fp32) and xsb=LN2(x2) (bf16).
// ---------------------------------------------------------------------------
__global__ __launch_bounds__(256, 2)
void proj_ln(const bf16* __restrict__ A, const bf16* __restrict__ Bw,
             const float* __restrict__ bias, const float* __restrict__ res,
             const float* __restrict__ n2w, const float* __restrict__ n2b,
             float* __restrict__ x2, bf16* __restrict__ xsb)
{
    extern __shared__ char dsm[];
    __shared__ float rs[128], rq[128], smu[128], sst[128];
    const uint32_t sbase = (smem_u32(dsm) + 127u) & ~127u;
    const int tid = threadIdx.x, lane = tid & 31, w = tid >> 5;
    const int wm = w & 3, wn = w >> 2;
    const int m0 = blockIdx.x * 128;

    if (tid < 128) { rs[tid] = 0.0f; rq[tid] = 0.0f; }

    float acc[2][8][4];
    #pragma unroll
    for (int i = 0; i < 2; i++) for (int j = 0; j < 8; j++) for (int q = 0; q < 4; q++)
        acc[i][j][q] = 0.0f;

    const int a_row = wm * 32 + ((lane >> 3) & 1) * 8 + (lane & 7);
    const int a_kof = (lane >> 4) * 8;
    const int b_row = wn * 64 + (lane >> 4) * 8 + (lane & 7);
    const int b_kof = ((lane >> 3) & 1) * 8;

    load_chunk<128>(sbase, A, Bw, m0, 0, 0, tid);
    load_chunk<128>(sbase + 32768u, A, Bw, m0, 0, 1, tid);
    asm volatile("cp.async.wait_group 1;" ::: "memory");
    __syncthreads();
    mma_chunk(sbase, sbase + 16384u, acc, a_row, a_kof, b_row, b_kof);
    asm volatile("cp.async.wait_group 0;" ::: "memory");
    __syncthreads();
    mma_chunk(sbase + 32768u, sbase + 49152u, acc, a_row, a_kof, b_row, b_kof);

    const int er = lane >> 2, ec = (lane & 3) * 2;
    float ps0[2] = {0, 0}, ps1[2] = {0, 0}, pq0[2] = {0, 0}, pq1[2] = {0, 0};
    #pragma unroll
    for (int mi = 0; mi < 2; mi++) {
        #pragma unroll
        for (int ns = 0; ns < 8; ns++) {
            int lr  = wm * 32 + mi * 16 + er;
            int col = wn * 64 + ns * 8 + ec;
            int row = m0 + lr;
            float2 bb = *(const float2*)&bias[col];
            float2 r0 = *(const float2*)&res[(size_t)row * 128 + col];
            float2 r1 = *(const float2*)&res[(size_t)(row + 8) * 128 + col];
            float v0 = acc[mi][ns][0] + bb.x + r0.x;
            float v1 = acc[mi][ns][1] + bb.y + r0.y;
            float v2 = acc[mi][ns][2] + bb.x + r1.x;
            float v3 = acc[mi][ns][3] + bb.y + r1.y;
            acc[mi][ns][0] = v0; acc[mi][ns][1] = v1;
            acc[mi][ns][2] = v2; acc[mi][ns][3] = v3;
            *(float2*)&x2[(size_t)row * 128 + col]       = make_float2(v0, v1);
            *(float2*)&x2[(size_t)(row + 8) * 128 + col] = make_float2(v2, v3);
            ps0[mi] += v0 + v1;          pq0[mi] += v0*v0 + v1*v1;
            ps1[mi] += v2 + v3;          pq1[mi] += v2*v2 + v3*v3;
        }
    }
    #pragma unroll
    for (int mi = 0; mi < 2; mi++) {
        int lr = wm * 32 + mi * 16 + er;
        atomicAdd(&rs[lr], ps0[mi]);      atomicAdd(&rq[lr], pq0[mi]);
        atomicAdd(&rs[lr + 8], ps1[mi]);  atomicAdd(&rq[lr + 8], pq1[mi]);
    }
    __syncthreads();
    if (tid < 128) {
        float mu  = rs[tid] * (1.0f / 128.0f);
        float var = rq[tid] * (1.0f / 128.0f) - mu * mu;
        smu[tid] = mu;
        sst[tid] = rsqrtf(var + 1e-5f);
    }
    __syncthreads();

    #pragma unroll
    for (int mi = 0; mi < 2; mi++) {
        #pragma unroll
        for (int ns = 0; ns < 8; ns++) {
            int lr  = wm * 32 + mi * 16 + er;
            int col = wn * 64 + ns * 8 + ec;
            int row = m0 + lr;
            float2 wv = *(const float2*)&n2w[col];
            float2 bv = *(const float2*)&n2b[col];
            float mu0 = smu[lr],     st0 = sst[lr];
            float mu1 = smu[lr + 8], st1 = sst[lr + 8];
            *(__nv_bfloat162*)&xsb[(size_t)row * 128 + col] =
                __floats2bfloat162_rn((acc[mi][ns][0] - mu0) * st0 * wv.x + bv.x,
                                      (acc[mi][ns][1] - mu0) * st0 * wv.y + bv.y);
            *(__nv_bfloat162*)&xsb[(size_t)(row + 8) * 128 + col] =
                __floats2bfloat162_rn((acc[mi][ns][2] - mu1) * st1 * wv.x + bv.x,
                                      (acc[mi][ns][3] - mu1) * st1 * wv.y + bv.y);
        }
    }
}

// ---------------------------------------------------------------------------
// Fused MLP (v1): out = x2 + fc2( gelu( fc1(xsb) ) ), h never hits DRAM.
// ---------------------------------------------------------------------------
__global__ __launch_bounds__(256, 1)
void mlp_kernel(const bf16* __restrict__ Axs,
                const bf16* __restrict__ w1, const float* __restrict__ b1,
                const bf16* __restrict__ w2, const float* __restrict__ b2,
                const float* __restrict__ x2, float* __restrict__ out)
{
    extern __shared__ char dsm[];
    const uint32_t sbase = (smem_u32(dsm) + 127u) & ~127u;
    const uint32_t As = sbase, Hs = sbase + 32768u, B0 = sbase + 65536u, B1 = sbase + 98304u;
    const int tid = threadIdx.x, lane = tid & 31, w = tid >> 5;
    const int wm = w & 3, wn = w >> 2;
    const int m0 = blockIdx.x * 128;

    const int a_row = wm * 32 + ((lane >> 3) & 1) * 8 + (lane & 7);
    const int a_kof = (lane >> 4) * 8;
    const int b_row = wn * 64 + (lane >> 4) * 8 + (lane & 7);
    const int b_kof = ((lane >> 3) & 1) * 8;
    const int er = lane >> 2, ec = (lane & 3) * 2;

    float oacc[2][8][4];
    #pragma unroll
    for (int i = 0; i < 2; i++) for (int j = 0; j < 8; j++) for (int q = 0; q < 4; q++)
        oacc[i][j][q] = 0.0f;

    load_tile(As, Axs + (size_t)m0 * 128, 128, tid);
    load_tile(B0, w1, 128, tid);
    asm volatile("cp.async.commit_group;" ::: "memory");
    load_tile(B1, w2, 512, tid);
    asm volatile("cp.async.commit_group;" ::: "memory");

    #pragma unroll 1
    for (int j = 0; j < 4; j++) {
        asm volatile("cp.async.wait_group 1;" ::: "memory");
        __syncthreads();

        float hacc[2][8][4];
        #pragma unroll
        for (int i = 0; i < 2; i++) for (int jj = 0; jj < 8; jj++) for (int q = 0; q < 4; q++)
            hacc[i][jj][q] = 0.0f;
        #pragma unroll
        for (int c = 0; c < 2; c++)
            mma_chunk(As + c * 16384u, B0 + c * 16384u, hacc, a_row, a_kof, b_row, b_kof);

        #pragma unroll
        for (int mi = 0; mi < 2; mi++) {
            #pragma unroll
            for (int ns = 0; ns < 8; ns++) {
                int lr  = wm * 32 + mi * 16 + er;
                int col = wn * 64 + ns * 8 + ec;
                float2 bb = *(const float2*)&b1[j * 128 + col];
                float v0 = hacc[mi][ns][0] + bb.x;
                float v1 = hacc[mi][ns][1] + bb.y;
                float v2 = hacc[mi][ns][2] + bb.x;
                float v3 = hacc[mi][ns][3] + bb.y;
                const float cst = 0.70710678118654752f;
                v0 = 0.5f * v0 * (1.0f + erff(v0 * cst));
                v1 = 0.5f * v1 * (1.0f + erff(v1 * cst));
                v2 = 0.5f * v2 * (1.0f + erff(v2 * cst));
                v3 = 0.5f * v3 * (1.0f + erff(v3 * cst));
                uint32_t ch = (uint32_t)(col >> 6) * 16384u;
                int cc = col & 63;
                uint32_t bo0 = (uint32_t)(lr * 128 + cc * 2);
                uint32_t bo1 = (uint32_t)((lr + 8) * 128 + cc * 2);
                uint32_t ad0 = Hs + ch + (bo0 ^ ((bo0 >> 3) & 0x70));
                uint32_t ad1 = Hs + ch + (bo1 ^ ((bo1 >> 3) & 0x70));
                __nv_bfloat162 p0 = __floats2bfloat162_rn(v0, v1);
                __nv_bfloat162 p1 = __floats2bfloat162_rn(v2, v3);
                asm volatile("st.shared.b32 [%0], %1;" :: "r"(ad0), "r"(*(uint32_t*)&p0));
                asm volatile("st.shared.b32 [%0], %1;" :: "r"(ad1), "r"(*(uint32_t*)&p1));
            }
        }
        __syncthreads();
        if (j < 3) {
            load_tile(B0, w1 + (size_t)(j + 1) * 128 * 128, 128, tid);
            asm volatile("cp.async.commit_group;" ::: "memory");
        }
        if (j < 3) { asm volatile("cp.async.wait_group 1;" ::: "memory"); }
        else       { asm volatile("cp.async.wait_group 0;" ::: "memory"); }
        __syncthreads();

        #pragma unroll
        for (int c = 0; c < 2; c++)
            mma_chunk(Hs + c * 16384u, B1 + c * 16384u, oacc, a_row, a_kof, b_row, b_kof);
        __syncthreads();
        if (j < 3) {
            load_tile(B1, w2 + (size_t)(j + 1) * 128, 512, tid);
            asm volatile("cp.async.commit_group;" ::: "memory");
        }
    }

    #pragma unroll
    for (int mi = 0; mi < 2; mi++) {
        #pragma unroll
        for (int ns = 0; ns < 8; ns++) {
            int lr  = wm * 32 + mi * 16 + er;
            int col = wn * 64 + ns * 8 + ec;
            int row = m0 + lr;
            float2 bb = *(const float2*)&b2[col];
            float2 r0 = *(const float2*)&x2[(size_t)row * 128 + col];
            float2 r1 = *(const float2*)&x2[(size_t)(row + 8) * 128 + col];
            *(float2*)&out[(size_t)row * 128 + col] =
                make_float2(oacc[mi][ns][0] + bb.x + r0.x, oacc[mi][ns][1] + bb.y + r0.y);
            *(float2*)&out[(size_t)(row + 8) * 128 + col] =
                make_float2(oacc[mi][ns][2] + bb.x + r1.x, oacc[mi][ns][3] + bb.y + r1.y);
        }
    }
}

// ---------------------------------------------------------------------------
extern "C" void kernel_launch(void* const* d_in, const int* in_sizes, int n_in,
                              void* d_out, int out_size)
{
    const float* x      = (const float*)d_in[0];
    const float* n1w    = (const float*)d_in[1];
    const float* n1b    = (const float*)d_in[2];
    const float* qkvw   = (const float*)d_in[3];
    const float* qkvb   = (const float*)d_in[4];
    const float* rpb    = (const float*)d_in[5];
    const float* projw  = (const float*)d_in[6];
    const float* projb  = (const float*)d_in[7];
    const float* n2w    = (const float*)d_in[8];
    const float* n2b    = (const float*)d_in[9];
    const float* fc1w   = (const float*)d_in[10];
    const float* fc1b   = (const float*)d_in[11];
    const float* fc2w   = (const float*)d_in[12];
    const float* fc2b   = (const float*)d_in[13];
    float* out = (float*)d_out;

    bf16 *xsb, *qkvb_s, *attnb, *wqkv, *wproj, *w1, *w2;
    float *x2;
    cudaGetSymbolAddress((void**)&xsb,    g_xsb);
    cudaGetSymbolAddress((void**)&qkvb_s, g_qkvb);
    cudaGetSymbolAddress((void**)&attnb,  g_attnb);
    cudaGetSymbolAddress((void**)&x2,     g_x2);
    cudaGetSymbolAddress((void**)&wqkv,   g_wqkv);
    cudaGetSymbolAddress((void**)&wproj,  g_wproj);
    cudaGetSymbolAddress((void**)&w1,     g_w1);
    cudaGetSymbolAddress((void**)&w2,     g_w2);

    const int SMEM_G = 65536 + 128;
    const int SMEM_M = 131072 + 128;
    cudaFuncSetAttribute(gemm_qkv,   cudaFuncAttributeMaxDynamicSharedMemorySize, SMEM_G);
    cudaFuncSetAttribute(proj_ln,    cudaFuncAttributeMaxDynamicSharedMemorySize, SMEM_G);
    cudaFuncSetAttribute(mlp_kernel, cudaFuncAttributeMaxDynamicSharedMemorySize, SMEM_M);

    // 0. weights -> bf16
    cvt_all<<<768, 256>>>(qkvw, projw, fc1w, fc2w, wqkv, wproj, w1, w2);
    // 1. LN1 -> bf16
    ln_kernel<<<M_TOK / 8, 256>>>(x, n1w, n1b, xsb);
    // 2. QKV projection -> bf16
    gemm_qkv<<<dim3(3, M_TOK / 128), 256, SMEM_G>>>(xsb, wqkv, qkvb, qkvb_s);
    // 3. attention -> bf16 (d-split, packed bf16x2 smem)
    attn_kernel<<<M_TOK / 32, 256>>>(qkvb_s, rpb, attnb);
    // 4. proj + residual + LN2 -> x2 (fp32) + xsb (bf16)
    proj_ln<<<M_TOK / 128, 256, SMEM_G>>>(attnb, wproj, projb, x, n2w, n2b, x2, xsb);
    // 5. fused MLP -> out
    mlp_kernel<<<M_TOK / 128, 256, SMEM_M>>>(xsb, w1, fc1b, w2, fc2b, x2, out);
}